// round 7
// baseline (speedup 1.0000x reference)
#include <cuda_runtime.h>
#include <cuda_bf16.h>

// Problem constants (match reference)
#define N_ROWS     262144
#define NUM_CLS    80
#define CONF_TH    0.25f
#define K_ROWS     131072   // int(N * 0.5)

#define GRID_MAIN  608      // 152 SMs * 4 resident blocks -> single wave
#define BLK        256
#define ROW_BYTES  (NUM_CLS * 4)   // 320 B per row

// Device-global state (statically initialized; last block re-arms after
// producing the output -> identical initial state for every replay).
__device__ int    g_first_bad = K_ROWS;   // first row with max < CONF (K_ROWS if none)
__device__ double g_sum       = 0.0;      // optimistic sum of scores >= CONF
__device__ unsigned int g_done = 0;       // completed-block counter

// Row max for one row, 4-lane cooperative (5 float4 per thread).
__device__ __forceinline__ float row_max4(const float4* __restrict__ rp, int sub) {
    float4 v0 = __ldg(&rp[sub]);
    float4 v1 = __ldg(&rp[sub + 4]);
    float4 v2 = __ldg(&rp[sub + 8]);
    float4 v3 = __ldg(&rp[sub + 12]);
    float4 v4 = __ldg(&rp[sub + 16]);
    float m = fmaxf(fmaxf(v0.x, v0.y), fmaxf(v0.z, v0.w));
    m = fmaxf(m, fmaxf(fmaxf(v1.x, v1.y), fmaxf(v1.z, v1.w)));
    m = fmaxf(m, fmaxf(fmaxf(v2.x, v2.y), fmaxf(v2.z, v2.w)));
    m = fmaxf(m, fmaxf(fmaxf(v3.x, v3.y), fmaxf(v3.z, v3.w)));
    m = fmaxf(m, fmaxf(fmaxf(v4.x, v4.y), fmaxf(v4.z, v4.w)));
    m = fmaxf(m, __shfl_xor_sync(0xFFFFFFFFu, m, 1));
    m = fmaxf(m, __shfl_xor_sync(0xFFFFFFFFu, m, 2));
    return m;
}

// ---------------------------------------------------------------------------
// Single persistent kernel, one resident wave (__launch_bounds__(256, 4)
// caps registers at 64/thread so 4 blocks/SM is guaranteed).
// Main pass: 4 threads per row, TWO rows per iteration (10 front-batched
// LDG.128 per thread -> high MLP). Per row (sub==0 lane):
//   - atomicMin of first row index whose max < CONF
//   - accumulate score into per-thread double if >= CONF
// Rows < CONF never contribute to the reference answer (its loop breaks
// there), so summing only rows >= CONF over-counts exactly the >=CONF rows
// at indices >= first_bad; the last block recomputes and subtracts those
// (empty in the common case first_bad == K_ROWS).
// ---------------------------------------------------------------------------
__global__ __launch_bounds__(BLK, 4) void k_main(const float* __restrict__ pr,
                                                 float* __restrict__ out) {
    __shared__ double swsum[BLK / 32];
    __shared__ bool   s_last;

    const int sub      = threadIdx.x & 3;               // lane within 4-lane group
    const int lane     = threadIdx.x & 31;
    const int wid      = threadIdx.x >> 5;
    const int group    = (blockIdx.x * BLK + threadIdx.x) >> 2;   // 0..38911
    const int n_groups = (GRID_MAIN * BLK) >> 2;        // 38912
    const int row_step = n_groups * 2;                  // 2 rows per iteration

    // byte-stride pointer walk: avoids 64-bit IMAD per row in the hot loop
    const char* base = reinterpret_cast<const char*>(pr)
                     + (size_t)(group * 2) * ROW_BYTES;
    const size_t step_bytes = (size_t)row_step * ROW_BYTES;

    double acc = 0.0;

    for (int row = group * 2; row < K_ROWS; row += row_step, base += step_bytes) {
        const float4* rpA = reinterpret_cast<const float4*>(base);
        const float4* rpB = reinterpret_cast<const float4*>(base + ROW_BYTES);

        // front-batch both rows' loads (10 independent LDG.128)
        float4 a0 = __ldg(&rpA[sub]);
        float4 a1 = __ldg(&rpA[sub + 4]);
        float4 a2 = __ldg(&rpA[sub + 8]);
        float4 a3 = __ldg(&rpA[sub + 12]);
        float4 a4 = __ldg(&rpA[sub + 16]);
        float4 b0 = __ldg(&rpB[sub]);
        float4 b1 = __ldg(&rpB[sub + 4]);
        float4 b2 = __ldg(&rpB[sub + 8]);
        float4 b3 = __ldg(&rpB[sub + 12]);
        float4 b4 = __ldg(&rpB[sub + 16]);

        float ma = fmaxf(fmaxf(a0.x, a0.y), fmaxf(a0.z, a0.w));
        ma = fmaxf(ma, fmaxf(fmaxf(a1.x, a1.y), fmaxf(a1.z, a1.w)));
        ma = fmaxf(ma, fmaxf(fmaxf(a2.x, a2.y), fmaxf(a2.z, a2.w)));
        ma = fmaxf(ma, fmaxf(fmaxf(a3.x, a3.y), fmaxf(a3.z, a3.w)));
        ma = fmaxf(ma, fmaxf(fmaxf(a4.x, a4.y), fmaxf(a4.z, a4.w)));
        float mb = fmaxf(fmaxf(b0.x, b0.y), fmaxf(b0.z, b0.w));
        mb = fmaxf(mb, fmaxf(fmaxf(b1.x, b1.y), fmaxf(b1.z, b1.w)));
        mb = fmaxf(mb, fmaxf(fmaxf(b2.x, b2.y), fmaxf(b2.z, b2.w)));
        mb = fmaxf(mb, fmaxf(fmaxf(b3.x, b3.y), fmaxf(b3.z, b3.w)));
        mb = fmaxf(mb, fmaxf(fmaxf(b4.x, b4.y), fmaxf(b4.z, b4.w)));

        ma = fmaxf(ma, __shfl_xor_sync(0xFFFFFFFFu, ma, 1));
        ma = fmaxf(ma, __shfl_xor_sync(0xFFFFFFFFu, ma, 2));
        mb = fmaxf(mb, __shfl_xor_sync(0xFFFFFFFFu, mb, 1));
        mb = fmaxf(mb, __shfl_xor_sync(0xFFFFFFFFu, mb, 2));

        if (sub == 0) {
            if (ma < CONF_TH) atomicMin(&g_first_bad, row);
            else              acc += (double)ma;
            if (mb < CONF_TH) atomicMin(&g_first_bad, row + 1);
            else              acc += (double)mb;
        }
    }

    // block reduction of the optimistic sum (only sub==0 lanes nonzero)
    #pragma unroll
    for (int o = 16; o; o >>= 1)
        acc += __shfl_xor_sync(0xFFFFFFFFu, acc, o);
    if (lane == 0) swsum[wid] = acc;
    __syncthreads();

    if (threadIdx.x == 0) {
        double s = 0.0;
        #pragma unroll
        for (int i = 0; i < BLK / 32; i++) s += swsum[i];
        atomicAdd(&g_sum, s);
        __threadfence();                                // publish g_sum / g_first_bad
        unsigned int prev = atomicAdd(&g_done, 1u);
        s_last = (prev == GRID_MAIN - 1);
    }
    __syncthreads();
    if (!s_last) return;

    // ---- last block: correction + writeback + re-arm ----
    // Recompute maxima of rows >= first_bad directly from gmem (rare path;
    // empty when first_bad == K_ROWS). 4 lanes per row, 64 rows per pass.
    __shared__ double sdata[BLK / 32];
    const int fb = g_first_bad;

    double c = 0.0;
    const int grp = threadIdx.x >> 2;                   // 0..63
    for (int i = fb + grp; i < K_ROWS; i += BLK / 4) {
        const float4* rp = reinterpret_cast<const float4*>(pr + (size_t)i * NUM_CLS);
        float m = row_max4(rp, sub);
        if (sub == 0 && m >= CONF_TH) c += (double)m;   // over-counted rows
    }
    #pragma unroll
    for (int o = 16; o; o >>= 1)
        c += __shfl_xor_sync(0xFFFFFFFFu, c, o);
    if (lane == 0) sdata[wid] = c;
    __syncthreads();

    if (threadIdx.x == 0) {
        double corr = 0.0;
        #pragma unroll
        for (int i = 0; i < BLK / 32; i++) corr += sdata[i];
        out[0] = (float)(g_sum - corr);
        // re-arm for the next (identical) invocation
        g_first_bad = K_ROWS;
        g_sum  = 0.0;
        g_done = 0u;
    }
}

extern "C" void kernel_launch(void* const* d_in, const int* in_sizes, int n_in,
                              void* d_out, int out_size) {
    const float* post_result = (const float*)d_in[0];
    float* out = (float*)d_out;

    k_main<<<GRID_MAIN, BLK>>>(post_result, out);
}